// round 16
// baseline (speedup 1.0000x reference)
#include <cuda_runtime.h>

#define NN   2048
#define MEM  1024
#define NCTA 128
#define TPB  256

typedef unsigned long long ull;

// Persistent device scratch (allocation-free rule: __device__ globals).
__device__ __align__(16) float g_Gx[NN * 5 * MEM];  // 40 MB input projection
__device__ __align__(16) float g_h[MEM];            // recurrent hidden broadcast
__device__ __align__(16) float g_v[MEM];            // z*tanh(c) broadcast
__device__ __align__(128) unsigned g_bar;           // single arrival counter
                                                    // (proven topology; multi-
                                                    // counter variants hang)

__device__ __forceinline__ float tanhfast(float x) {
    float y; asm("tanh.approx.f32 %0, %1;" : "=f"(y) : "f"(x)); return y;
}
__device__ __forceinline__ float sigfast(float x) {
    return 0.5f * tanhfast(0.5f * x) + 0.5f;
}

// SHFL-tree reduction (redux.sync.add.f32 does NOT exist on sm_103 —
// ptxas-confirmed round 14; 5x26cyc is the fp32 warp-reduce floor).
__device__ __forceinline__ float warpSum(float v) {
#pragma unroll
    for (int o = 16; o > 0; o >>= 1) v += __shfl_down_sync(0xffffffffu, v, o);
    return v;
}

__device__ __forceinline__ void fma2(ull& acc, ull a, ull b) {
    asm("fma.rn.f32x2 %0, %1, %2, %0;" : "+l"(acc) : "l"(a), "l"(b));
}
__device__ __forceinline__ float2 unpk(ull p) {
    float2 r; asm("mov.b64 {%0,%1}, %2;" : "=f"(r.x), "=f"(r.y) : "l"(p)); return r;
}
__device__ __forceinline__ ull pk(float a, float b) {
    ull p; asm("mov.b64 %0, {%1,%2};" : "=l"(p) : "f"(a), "f"(b)); return p;
}
__device__ __forceinline__ unsigned ld_acquire_u32(const unsigned* p) {
    unsigned v;
    asm volatile("ld.acquire.gpu.global.u32 %0, [%1];" : "=r"(v) : "l"(p));
    return v;
}
__device__ __forceinline__ void red_release_add(unsigned* p, unsigned v) {
    asm volatile("red.release.gpu.global.add.u32 [%0], %1;" :: "l"(p), "r"(v)
                 : "memory");
}
__device__ __forceinline__ void stcg_f32(float* p, float v) {
    asm volatile("st.global.cg.f32 [%0], %1;" :: "l"(p), "f"(v) : "memory");
}

// 4-lane pipelined poll (warp 0 only): lanes 0..3 run independent dependent
// ld.acquire chains -> counter sampled ~4x per L2 round trip. 512 pollers
// chip-wide on one line (~0.9 req/cyc) — at, not beyond, the LTS single-line
// service rate. Observing lane's acquire + the CTA barrier after this call
// give the transitive happens-before for the payload loads.
__device__ __forceinline__ void poll4(const unsigned* p, unsigned tgt) {
    const int lane = threadIdx.x & 31;
    for (;;) {
        unsigned v = 0;
        if (lane < 4) v = ld_acquire_u32(p);
        if (__any_sync(0xffffffffu, v >= tgt)) break;
    }
}

// ---------------------------------------------------------------------------
// Kernel 1: Gx = inputs @ Wx + bx   (2048 x 1024) @ (1024 x 5120)
// Classic 128x128x8 SGEMM (~120us total — near-free vs the scan).
// Block (0,0) also resets the scan arrival counter for this graph replay.
// ---------------------------------------------------------------------------
__global__ void __launch_bounds__(256) gemm_gx_kernel(
    const float* __restrict__ A,   // inputs (2048,1024)
    const float* __restrict__ B,   // Wx (1024,5120)
    const float* __restrict__ bx)  // (5120,)
{
    if (blockIdx.x == 0 && blockIdx.y == 0 && threadIdx.x == 0) g_bar = 0u;

    __shared__ float As[8][128];
    __shared__ float Bs[8][132];

    const int tid  = threadIdx.x;
    const int tx   = tid & 15;
    const int ty   = tid >> 4;
    const int arow = tid >> 1;
    const int akc  = (tid & 1) << 2;
    const int bkr  = tid >> 5;
    const int bcol = (tid & 31) << 2;

    const int m0 = blockIdx.y << 7;
    const int n0 = blockIdx.x << 7;

    const float* Aptr = A + (m0 + arow) * 1024 + akc;
    const float* Bptr = B + bkr * 5120 + n0 + bcol;

    float acc[8][8];
#pragma unroll
    for (int i = 0; i < 8; ++i)
#pragma unroll
        for (int j = 0; j < 8; ++j) acc[i][j] = 0.0f;

    for (int kt = 0; kt < 1024; kt += 8) {
        const float4 av = __ldg((const float4*)(Aptr + kt));
        const float4 bv = __ldg((const float4*)(Bptr + kt * 5120));
        As[akc + 0][arow] = av.x;
        As[akc + 1][arow] = av.y;
        As[akc + 2][arow] = av.z;
        As[akc + 3][arow] = av.w;
        *(float4*)&Bs[bkr][bcol] = bv;
        __syncthreads();

#pragma unroll
        for (int k = 0; k < 8; ++k) {
            float ar[8], br[8];
            *(float4*)(ar)     = *(const float4*)&As[k][ty * 8];
            *(float4*)(ar + 4) = *(const float4*)&As[k][ty * 8 + 4];
            *(float4*)(br)     = *(const float4*)&Bs[k][tx * 8];
            *(float4*)(br + 4) = *(const float4*)&Bs[k][tx * 8 + 4];
#pragma unroll
            for (int i = 0; i < 8; ++i)
#pragma unroll
                for (int j = 0; j < 8; ++j) acc[i][j] += ar[i] * br[j];
        }
        __syncthreads();
    }

    const int crow = m0 + ty * 8;
    const int ccol = n0 + tx * 8;
    float bxv[8];
    *(float4*)(bxv)     = __ldg((const float4*)&bx[ccol]);
    *(float4*)(bxv + 4) = __ldg((const float4*)&bx[ccol + 4]);
#pragma unroll
    for (int i = 0; i < 8; ++i) {
        float4 c0 = make_float4(acc[i][0] + bxv[0], acc[i][1] + bxv[1],
                                acc[i][2] + bxv[2], acc[i][3] + bxv[3]);
        float4 c1 = make_float4(acc[i][4] + bxv[4], acc[i][5] + bxv[5],
                                acc[i][6] + bxv[6], acc[i][7] + bxv[7]);
        *(float4*)&g_Gx[(size_t)(crow + i) * 5120 + ccol]     = c0;
        *(float4*)&g_Gx[(size_t)(crow + i) * 5120 + ccol + 4] = c1;
    }
}

// ---------------------------------------------------------------------------
// Kernel 2: persistent scan. 128 CTAs x 8 warps; warp w of CTA b owns state
// dim m = 8b + w (4 Wh gate columns + 1 Wum column in registers, packed
// f32x2). Critical-path-ordered step:
//   phase 1: z-column dot FIRST -> publish v = sig(gxz_f + s3) * tcp, where
//   gxz_f (gxz+bh_z+pzc*c) and tcp = tanh(c) were PRECOMPUTED off-path at
//   the end of the previous step — the z-tail after the reduce is just one
//   sigmoid + mul. i/o/f dots + gates run in the v-barrier SHADOW.
//   phase 2: Wum dot -> u,c,o,h -> publish h; then precompute tcp / pz / pi
//   / pf for the next step (hides under the next h-poll).
// Sync: round-3/9/11/12-proven single counter; per phase, per-warp st.cg,
// bar, ONE red.release by tid0; 4-lane poll in warp 0. All CTAs co-resident.
// ---------------------------------------------------------------------------
__global__ void __launch_bounds__(TPB, 1) scan_kernel(
    const float* __restrict__ Wh,  const float* __restrict__ bh,
    const float* __restrict__ Wum, const float* __restrict__ bum,
    const float* __restrict__ pic, const float* __restrict__ pfc,
    const float* __restrict__ poc, const float* __restrict__ pzc,
    float* __restrict__ out)
{
    __shared__ __align__(16) float xbuf[MEM];   // broadcast h (ph1) / v (ph2)

    const int tid  = threadIdx.x;
    const int w    = tid >> 5;
    const int lane = tid & 31;
    const int m    = blockIdx.x * 8 + w;        // this warp's state dim

    // ---- load + pack recurrent weights into registers (once) ----
    ulonglong2 wrp[8][4];   // Wh columns {g*MEM+m}, packed pairs over k
    ulonglong2 wmp[8];      // Wum column m
#pragma unroll
    for (int i = 0; i < 8; ++i) {
        const int k = (i * 32 + lane) * 4;
#pragma unroll
        for (int g = 0; g < 4; ++g) {
            const int col = g * MEM + m;
            const float a = __ldg(&Wh[(size_t)(k + 0) * (4 * MEM) + col]);
            const float b = __ldg(&Wh[(size_t)(k + 1) * (4 * MEM) + col]);
            const float c = __ldg(&Wh[(size_t)(k + 2) * (4 * MEM) + col]);
            const float d = __ldg(&Wh[(size_t)(k + 3) * (4 * MEM) + col]);
            wrp[i][g].x = pk(a, b);
            wrp[i][g].y = pk(c, d);
        }
        const float a = __ldg(&Wum[(size_t)(k + 0) * MEM + m]);
        const float b = __ldg(&Wum[(size_t)(k + 1) * MEM + m]);
        const float c = __ldg(&Wum[(size_t)(k + 2) * MEM + m]);
        const float d = __ldg(&Wum[(size_t)(k + 3) * MEM + m]);
        wmp[i].x = pk(a, b);
        wmp[i].y = pk(c, d);
    }

    // per-dim constants (lane 0 of each warp)
    float bh_i = 0, bh_o = 0, bh_f = 0, bh_z = 0, bum_v = 0;
    float pic_v = 0, pfc_v = 0, poc_v = 0, pzc_v = 0;
    if (lane == 0) {
        bh_i = bh[m];           bh_o = bh[MEM + m];
        bh_f = bh[2 * MEM + m]; bh_z = bh[3 * MEM + m];
        bum_v = bum[m];
        pic_v = pic[m]; pfc_v = pfc[m]; poc_v = poc[m]; pzc_v = pzc[m];
    }
    // recurrent state + off-path precomputed derivatives of c
    float cp = 0.0f, hmx = -3.402823466e38f;
    float tcp = 0.0f;                   // tanh(cp)
    float pz_cp = 0.0f, pi_cp = 0.0f, pf_cp = 0.0f;   // pzc*cp, pic*cp, pfc*cp

    float4* xbuf4 = (float4*)xbuf;
    __syncthreads();

#pragma unroll 1
    for (unsigned t = 0; t < NN; ++t) {
        // Gx prefetch + bias/peephole folding (off-path: hides under h-poll)
        float gxz_f = 0, gxi_f = 0, gxf_f = 0, gxo_f = 0, gxu_f = 0;
        if (lane == 0) {
            const float* gx = g_Gx + (size_t)t * (5 * MEM) + m;
            const float gxi = __ldg(gx);
            const float gxo = __ldg(gx + MEM);
            const float gxf = __ldg(gx + 2 * MEM);
            const float gxz = __ldg(gx + 3 * MEM);
            const float gxu = __ldg(gx + 4 * MEM);
            gxz_f = gxz + bh_z + pz_cp;   // z-gate fully folded: tail = sig+mul
            gxi_f = gxi + bh_i + pi_cp;
            gxf_f = gxf + bh_f + pf_cp;
            gxo_f = gxo + bh_o;
            gxu_f = gxu + bum_v;
        }

        // ---- acquire h(t-1) ----
        if (t == 0) {
            xbuf4[tid] = make_float4(0.f, 0.f, 0.f, 0.f);
        } else {
            if (w == 0) poll4(&g_bar, 256u * t);
            __syncthreads();
            xbuf4[tid] = __ldcg(((const float4*)g_h) + tid);
        }
        __syncthreads();

        const ulonglong2* hp2 = (const ulonglong2*)xbuf;

        // ---- phase 1a: z-column dot ONLY -> publish v ASAP ----
        ull az0 = 0ull, az1 = 0ull;
#pragma unroll
        for (int i = 0; i < 8; ++i) {
            const ulonglong2 hp = hp2[i * 32 + lane];
            fma2(az0, hp.x, wrp[i][3].x);
            fma2(az1, hp.y, wrp[i][3].y);
        }
        const float2 ze = unpk(az0), zo = unpk(az1);
        const float s3 = warpSum(ze.x + ze.y + zo.x + zo.y);
        if (lane == 0) {
            stcg_f32(&g_v[m], sigfast(gxz_f + s3) * tcp);  // short z-tail
        }
        __syncthreads();                          // all 8 v-stores issued
        if (tid == 0) red_release_add(&g_bar, 1u);  // st -> bar -> release hb

        // ---- phase 1b (v-barrier shadow): i/o/f dots + gates for phase 2 ----
        ull acc[3][2] = {{0ull, 0ull}, {0ull, 0ull}, {0ull, 0ull}};
#pragma unroll
        for (int i = 0; i < 8; ++i) {
            const ulonglong2 hp = hp2[i * 32 + lane];
#pragma unroll
            for (int g = 0; g < 3; ++g) {
                fma2(acc[g][0], hp.x, wrp[i][g].x);
                fma2(acc[g][1], hp.y, wrp[i][g].y);
            }
        }
        const float2 e0 = unpk(acc[0][0]), o0 = unpk(acc[0][1]);
        const float2 e1 = unpk(acc[1][0]), o1 = unpk(acc[1][1]);
        const float2 e2 = unpk(acc[2][0]), o2 = unpk(acc[2][1]);
        const float s0 = warpSum(e0.x + e0.y + o0.x + o0.y);
        const float s1 = warpSum(e1.x + e1.y + o1.x + o1.y);
        const float s2 = warpSum(e2.x + e2.y + o2.x + o2.y);

        float iv = 0.f, fv = 0.f, opre = 0.f;
        if (lane == 0) {
            iv   = sigfast(gxi_f + s0);
            fv   = sigfast(gxf_f + s2);
            opre = gxo_f + s1;
        }

        // ---- v-barrier detect + acquire v(t) ----
        if (w == 0) poll4(&g_bar, 256u * t + 128u);
        __syncthreads();
        xbuf4[tid] = __ldcg(((const float4*)g_v) + tid);
        __syncthreads();

        // ---- phase 2: Wum dot, u/c/o/h, publish h ----
        ull b0 = 0ull, b1 = 0ull;
        const ulonglong2* vp2 = (const ulonglong2*)xbuf;
#pragma unroll
        for (int i = 0; i < 8; ++i) {
            const ulonglong2 vp = vp2[i * 32 + lane];
            fma2(b0, vp.x, wmp[i].x);
            fma2(b1, vp.y, wmp[i].y);
        }
        const float2 be = unpk(b0), bo = unpk(b1);
        const float sb = warpSum(be.x + be.y + bo.x + bo.y);

        float cc = 0.f;
        if (lane == 0) {
            const float u  = tanhfast(gxu_f + sb);
            cc = iv * u + fv * cp;
            const float oo = sigfast(opre + poc_v * cc);
            const float hh = oo * tanhfast(cc);
            stcg_f32(&g_h[m], hh);               // per-warp direct publish
            cp  = cc;
            hmx = fmaxf(hmx, hh);
        }
        __syncthreads();                          // all 8 h-stores issued
        if (tid == 0) red_release_add(&g_bar, 1u);

        // ---- off-path precompute for the next step's z-tail ----
        if (lane == 0) {
            tcp   = tanhfast(cc);
            pz_cp = pzc_v * cc;
            pi_cp = pic_v * cc;
            pf_cp = pfc_v * cc;
        }
        // next iteration's h-acquire performs the poll for 256*(t+1)
    }

    if (lane == 0) out[m] = hmx;
}

// ---------------------------------------------------------------------------
extern "C" void kernel_launch(void* const* d_in, const int* in_sizes, int n_in,
                              void* d_out, int out_size) {
    const float* inputs = (const float*)d_in[0];
    const float* Wx     = (const float*)d_in[1];
    const float* bx     = (const float*)d_in[2];
    const float* Wh     = (const float*)d_in[3];
    const float* bh     = (const float*)d_in[4];
    const float* Wum    = (const float*)d_in[5];
    const float* bum    = (const float*)d_in[6];
    const float* pic    = (const float*)d_in[7];
    const float* pfc    = (const float*)d_in[8];
    const float* poc    = (const float*)d_in[9];
    const float* pzc    = (const float*)d_in[10];
    float* out = (float*)d_out;

    dim3 gg(5120 / 128, 2048 / 128);
    gemm_gx_kernel<<<gg, 256>>>(inputs, Wx, bx);
    scan_kernel<<<NCTA, TPB>>>(Wh, bh, Wum, bum,
                               pic, pfc, poc, pzc, out);
}